// round 2
// baseline (speedup 1.0000x reference)
#include <cuda_runtime.h>
#include <math.h>

#define B_   128
#define CF   1024
#define R_   256
#define NATT 312
#define DV   300
#define NJ   624   // 2*NATT (Q rows then P rows)

// Scratch (static device globals; no runtime allocation)
__device__ float g_vv[NATT * DV];          // normalized V
__device__ float g_M[NJ * CF];             // [Q;P] = [vv@W1 ; vv@W2]
__device__ float g_norm[B_ * R_];          // per (b,r) column L2 norm of img
__device__ float g_C[(size_t)B_ * NJ * R_]; // batched GEMM output (~78 MB)

// ---------------------------------------------------------------------------
// vv = V / max(||V_row||, eps)
// ---------------------------------------------------------------------------
__global__ void vv_kernel(const float* __restrict__ V) {
    int i = blockIdx.x;          // 0..311
    int tid = threadIdx.x;       // 256 threads
    __shared__ float red[8];
    float s = 0.f;
    for (int v = tid; v < DV; v += 256) {
        float x = V[i * DV + v];
        s += x * x;
    }
    #pragma unroll
    for (int o = 16; o; o >>= 1) s += __shfl_xor_sync(0xffffffffu, s, o);
    if ((tid & 31) == 0) red[tid >> 5] = s;
    __syncthreads();
    if (tid == 0) {
        float t = 0.f;
        #pragma unroll
        for (int w = 0; w < 8; w++) t += red[w];
        red[0] = t;
    }
    __syncthreads();
    float inv = 1.f / fmaxf(sqrtf(red[0]), 1e-12f);
    for (int v = tid; v < DV; v += 256) g_vv[i * DV + v] = V[i * DV + v] * inv;
}

// ---------------------------------------------------------------------------
// norm[b,r] = || img[b,:,r] ||_2
// ---------------------------------------------------------------------------
__global__ void norm_kernel(const float* __restrict__ img) {
    int b = blockIdx.x;     // 128
    int r = threadIdx.x;    // 256
    const float* p = img + (size_t)b * CF * R_ + r;
    float s = 0.f;
    #pragma unroll 8
    for (int f = 0; f < CF; f++) {
        float v = p[(size_t)f * R_];
        s += v * v;
    }
    g_norm[b * R_ + r] = sqrtf(s);
}

// ---------------------------------------------------------------------------
// Generic tiled fp32 GEMM: C = A[MxK] * B[KxN] (row-major), batched over z on B/C.
// Block tile 128x128, BK=16, 256 threads, 8x8 per-thread micro-tile.
// N and ld* must be multiples of 4 (float4 loads). M guarded; K guarded if GUARD_K.
// ---------------------------------------------------------------------------
template <bool GUARD_K>
__global__ void __launch_bounds__(256)
gemm128(const float* __restrict__ A, const float* __restrict__ B,
        float* __restrict__ C, int M, int N, int K,
        int lda, int ldb, int ldc, long strideB, long strideC) {
    const int bm = blockIdx.x * 128;
    const int bn = blockIdx.y * 128;
    const float* Bp = B + (size_t)blockIdx.z * strideB;
    float* Cp = C + (size_t)blockIdx.z * strideC;

    __shared__ float As[128][17];   // padded: conflict-free broadcast reads
    __shared__ float Bs[16][128];

    const int tid = threadIdx.x;
    const int tx = tid & 15;
    const int ty = tid >> 4;

    float acc[8][8];
    #pragma unroll
    for (int i = 0; i < 8; i++)
        #pragma unroll
        for (int j = 0; j < 8; j++) acc[i][j] = 0.f;

    for (int k0 = 0; k0 < K; k0 += 16) {
        // --- load A tile (128x16) ---
        #pragma unroll
        for (int it = 0; it < 2; it++) {
            int s = it * 256 + tid;          // 512 float4 slots
            int row = s >> 2;
            int kk4 = (s & 3) * 4;
            float4 v = make_float4(0.f, 0.f, 0.f, 0.f);
            int gr = bm + row, gk = k0 + kk4;
            if (gr < M) {
                if (!GUARD_K || gk + 3 < K) {
                    v = *(const float4*)(A + (size_t)gr * lda + gk);
                } else {
                    float t0 = (gk + 0 < K) ? A[(size_t)gr * lda + gk + 0] : 0.f;
                    float t1 = (gk + 1 < K) ? A[(size_t)gr * lda + gk + 1] : 0.f;
                    float t2 = (gk + 2 < K) ? A[(size_t)gr * lda + gk + 2] : 0.f;
                    float t3 = (gk + 3 < K) ? A[(size_t)gr * lda + gk + 3] : 0.f;
                    v = make_float4(t0, t1, t2, t3);
                }
            }
            As[row][kk4 + 0] = v.x;
            As[row][kk4 + 1] = v.y;
            As[row][kk4 + 2] = v.z;
            As[row][kk4 + 3] = v.w;
        }
        // --- load B tile (16x128) ---
        #pragma unroll
        for (int it = 0; it < 2; it++) {
            int s = it * 256 + tid;
            int kk = s >> 5;
            int n4 = (s & 31) * 4;
            float4 v = make_float4(0.f, 0.f, 0.f, 0.f);
            int gk = k0 + kk;
            if (!GUARD_K || gk < K)
                v = *(const float4*)(Bp + (size_t)gk * ldb + bn + n4);
            *(float4*)&Bs[kk][n4] = v;
        }
        __syncthreads();

        #pragma unroll
        for (int k = 0; k < 16; k++) {
            float a[8], bb[8];
            #pragma unroll
            for (int i = 0; i < 4; i++) {
                a[i]     = As[ty * 4 + i][k];
                a[4 + i] = As[64 + ty * 4 + i][k];
            }
            float4 b0 = *(float4*)&Bs[k][tx * 4];
            float4 b1 = *(float4*)&Bs[k][64 + tx * 4];
            bb[0] = b0.x; bb[1] = b0.y; bb[2] = b0.z; bb[3] = b0.w;
            bb[4] = b1.x; bb[5] = b1.y; bb[6] = b1.z; bb[7] = b1.w;
            #pragma unroll
            for (int i = 0; i < 8; i++)
                #pragma unroll
                for (int j = 0; j < 8; j++)
                    acc[i][j] = fmaf(a[i], bb[j], acc[i][j]);
        }
        __syncthreads();
    }

    // --- store ---
    #pragma unroll
    for (int i = 0; i < 8; i++) {
        int gr = bm + ((i < 4) ? (ty * 4 + i) : (64 + ty * 4 + i - 4));
        if (gr < M) {
            #pragma unroll
            for (int jj = 0; jj < 2; jj++) {
                int gc = bn + jj * 64 + tx * 4;
                float4 v = make_float4(acc[i][jj * 4 + 0], acc[i][jj * 4 + 1],
                                       acc[i][jj * 4 + 2], acc[i][jj * 4 + 3]);
                *(float4*)(Cp + (size_t)gr * ldc + gc) = v;
            }
        }
    }
}

// ---------------------------------------------------------------------------
// Pred[b,i] = sum_r softmax_r(C_top[b,i,:]/norm) * (C_bot[b,i,:]/norm)
// ---------------------------------------------------------------------------
__global__ void finalize_kernel(float* __restrict__ out) {
    int i = blockIdx.x;   // 312
    int b = blockIdx.y;   // 128
    int r = threadIdx.x;  // 256

    float inv = 1.f / fmaxf(g_norm[b * R_ + r], 1e-12f);
    float a = g_C[((size_t)b * NJ + i) * R_ + r] * inv;
    float p = g_C[((size_t)b * NJ + NATT + i) * R_ + r] * inv;

    __shared__ float redm[8], red1[8], red2[8];

    float m = a;
    #pragma unroll
    for (int o = 16; o; o >>= 1) m = fmaxf(m, __shfl_xor_sync(0xffffffffu, m, o));
    if ((r & 31) == 0) redm[r >> 5] = m;
    __syncthreads();
    if (r == 0) {
        float t = redm[0];
        #pragma unroll
        for (int w = 1; w < 8; w++) t = fmaxf(t, redm[w]);
        redm[0] = t;
    }
    __syncthreads();
    m = redm[0];

    float e = expf(a - m);
    float s1 = e;
    float s2 = e * p;
    #pragma unroll
    for (int o = 16; o; o >>= 1) {
        s1 += __shfl_xor_sync(0xffffffffu, s1, o);
        s2 += __shfl_xor_sync(0xffffffffu, s2, o);
    }
    if ((r & 31) == 0) { red1[r >> 5] = s1; red2[r >> 5] = s2; }
    __syncthreads();
    if (r == 0) {
        float t1 = 0.f, t2 = 0.f;
        #pragma unroll
        for (int w = 0; w < 8; w++) { t1 += red1[w]; t2 += red2[w]; }
        out[b * NATT + i] = t2 / t1;
    }
}

// ---------------------------------------------------------------------------
extern "C" void kernel_launch(void* const* d_in, const int* in_sizes, int n_in,
                              void* d_out, int out_size) {
    const float* img = (const float*)d_in[0];
    const float* V   = (const float*)d_in[1];
    const float* W1  = (const float*)d_in[2];
    const float* W2  = (const float*)d_in[3];
    float* out = (float*)d_out;

    void *p_vv, *p_M, *p_C;
    cudaGetSymbolAddress(&p_vv, g_vv);
    cudaGetSymbolAddress(&p_M, g_M);
    cudaGetSymbolAddress(&p_C, g_C);
    float* vv = (float*)p_vv;
    float* Mm = (float*)p_M;
    float* Cc = (float*)p_C;

    vv_kernel<<<NATT, 256>>>(V);
    norm_kernel<<<B_, 256>>>(img);

    // Q = vv @ W1  -> g_M rows [0,312)
    {
        dim3 g((NATT + 127) / 128, CF / 128, 1);
        gemm128<true><<<g, 256>>>(vv, W1, Mm, NATT, CF, DV, DV, CF, CF, 0, 0);
    }
    // P = vv @ W2  -> g_M rows [312,624)
    {
        dim3 g((NATT + 127) / 128, CF / 128, 1);
        gemm128<true><<<g, 256>>>(vv, W2, Mm + (size_t)NATT * CF, NATT, CF, DV, DV, CF, CF, 0, 0);
    }
    // Batched: C_b = M @ img_b   (624x256x1024 per b, 128 batches)
    {
        dim3 g((NJ + 127) / 128, R_ / 128, B_);
        gemm128<false><<<g, 256>>>(Mm, img, Cc, NJ, R_, CF, CF, R_, R_,
                                   (long)CF * R_, (long)NJ * R_);
    }
    finalize_kernel<<<dim3(NATT, B_), 256>>>(out);
}

// round 10
// speedup vs baseline: 2.3197x; 2.3197x over previous
#include <cuda_runtime.h>
#include <cuda_bf16.h>
#include <math.h>
#include <stdint.h>

#define B_   128
#define CF   1024
#define R_   256
#define NATT 312
#define DV   300
#define NJP  640   // padded interleaved rows (row 2i=Q_i, 2i+1=P_i)

// ---------------- device scratch ----------------
__device__ float g_vv[NATT * DV];
__device__ float g_M[NJP * CF];                      // fp32 interleaved Q/P
__device__ __nv_bfloat16 g_Mh[NJP * CF];
__device__ __nv_bfloat16 g_Ml[NJP * CF];
__device__ __nv_bfloat16 g_Th[(size_t)B_ * R_ * CF]; // img^T hi [b][r][f]
__device__ __nv_bfloat16 g_Tl[(size_t)B_ * R_ * CF]; // img^T lo
__device__ float g_np[32 * B_ * R_];
__device__ float g_invn[B_ * R_];

// ---------------- smem layout (main kernel) ----------------
#define PITCH  144          // 128B data + 16B pad: LDSM rows hit distinct banks
#define SA_H   0            // 128 rows * 144
#define SA_L   18432
#define SB_H   36864        // 256 rows * 144
#define SB_L   73728
#define STAGE  110592
#define INV_OFF (2 * STAGE)               // 221184
#define SMEM_TOTAL (INV_OFF + 1024)       // 222208
#define CPITCH 257                        // epilogue fp32 C pitch (floats)

// ---------------- PTX helpers (all plain sm_80+ PTX) ----------------
__device__ __forceinline__ uint32_t smem_u32(const void* p) {
    uint32_t a;
    asm("{ .reg .u64 t; cvta.to.shared.u64 t, %1; cvt.u32.u64 %0, t; }" : "=r"(a) : "l"(p));
    return a;
}
__device__ __forceinline__ void cp16(uint32_t dst, const void* src) {
    asm volatile("cp.async.cg.shared.global [%0], [%1], 16;" :: "r"(dst), "l"(src));
}
#define CP_COMMIT() asm volatile("cp.async.commit_group;" ::: "memory")
#define CP_WAIT(n)  asm volatile("cp.async.wait_group %0;" :: "n"(n) : "memory")

__device__ __forceinline__ void ldsm4(uint32_t& r0, uint32_t& r1, uint32_t& r2,
                                      uint32_t& r3, uint32_t addr) {
    asm volatile("ldmatrix.sync.aligned.m8n8.x4.shared.b16 {%0,%1,%2,%3}, [%4];"
                 : "=r"(r0), "=r"(r1), "=r"(r2), "=r"(r3) : "r"(addr));
}
__device__ __forceinline__ void mma16816(float* d, const uint32_t* a, const uint32_t* b) {
    asm volatile("mma.sync.aligned.m16n8k16.row.col.f32.bf16.bf16.f32 "
                 "{%0,%1,%2,%3}, {%4,%5,%6,%7}, {%8,%9}, {%0,%1,%2,%3};"
                 : "+f"(d[0]), "+f"(d[1]), "+f"(d[2]), "+f"(d[3])
                 : "r"(a[0]), "r"(a[1]), "r"(a[2]), "r"(a[3]), "r"(b[0]), "r"(b[1]));
}

// ---------------------------------------------------------------------------
// vv = V / max(||row||, eps)
// ---------------------------------------------------------------------------
__global__ void vv_kernel(const float* __restrict__ V) {
    int i = blockIdx.x, tid = threadIdx.x;
    __shared__ float red[8];
    float s = 0.f;
    for (int v = tid; v < DV; v += 256) { float x = V[i * DV + v]; s += x * x; }
    #pragma unroll
    for (int o = 16; o; o >>= 1) s += __shfl_xor_sync(0xffffffffu, s, o);
    if ((tid & 31) == 0) red[tid >> 5] = s;
    __syncthreads();
    if (tid == 0) { float t = 0.f; for (int w = 0; w < 8; w++) t += red[w]; red[0] = t; }
    __syncthreads();
    float inv = 1.f / fmaxf(sqrtf(red[0]), 1e-12f);
    for (int v = tid; v < DV; v += 256) g_vv[i * DV + v] = V[i * DV + v] * inv;
}

// ---------------------------------------------------------------------------
// Small GEMMs: z=0: Q=vv@W1 -> even rows of g_M; z=1: P=vv@W2 -> odd rows
// ---------------------------------------------------------------------------
__global__ void __launch_bounds__(256)
gemm_small(const float* __restrict__ W1, const float* __restrict__ W2) {
    const int bm = blockIdx.x * 128;
    const int bn = blockIdx.y * 128;
    const int z = blockIdx.z;
    const float* A = g_vv;
    const float* Bp = z ? W2 : W1;
    float* Cp = g_M + z * CF;
    const int M = NATT, K = DV, lda = DV, ldb = CF, ldc = 2 * CF;

    __shared__ float As[128][17];
    __shared__ float Bs[16][128];
    const int tid = threadIdx.x;
    const int tx = tid & 15, ty = tid >> 4;
    float acc[8][8];
    #pragma unroll
    for (int i = 0; i < 8; i++)
        #pragma unroll
        for (int j = 0; j < 8; j++) acc[i][j] = 0.f;

    for (int k0 = 0; k0 < K; k0 += 16) {
        #pragma unroll
        for (int it = 0; it < 2; it++) {
            int s = it * 256 + tid;
            int row = s >> 2, kk4 = (s & 3) * 4;
            float4 v = make_float4(0.f, 0.f, 0.f, 0.f);
            int gr = bm + row, gk = k0 + kk4;
            if (gr < M) {
                if (gk + 3 < K) v = *(const float4*)(A + (size_t)gr * lda + gk);
                else {
                    float t0 = (gk + 0 < K) ? A[(size_t)gr * lda + gk + 0] : 0.f;
                    float t1 = (gk + 1 < K) ? A[(size_t)gr * lda + gk + 1] : 0.f;
                    float t2 = (gk + 2 < K) ? A[(size_t)gr * lda + gk + 2] : 0.f;
                    float t3 = (gk + 3 < K) ? A[(size_t)gr * lda + gk + 3] : 0.f;
                    v = make_float4(t0, t1, t2, t3);
                }
            }
            As[row][kk4 + 0] = v.x; As[row][kk4 + 1] = v.y;
            As[row][kk4 + 2] = v.z; As[row][kk4 + 3] = v.w;
        }
        #pragma unroll
        for (int it = 0; it < 2; it++) {
            int s = it * 256 + tid;
            int kk = s >> 5, n4 = (s & 31) * 4;
            float4 v = make_float4(0.f, 0.f, 0.f, 0.f);
            int gk = k0 + kk;
            if (gk < K) v = *(const float4*)(Bp + (size_t)gk * ldb + bn + n4);
            *(float4*)&Bs[kk][n4] = v;
        }
        __syncthreads();
        #pragma unroll
        for (int k = 0; k < 16; k++) {
            float a[8], bb[8];
            #pragma unroll
            for (int i = 0; i < 4; i++) {
                a[i] = As[ty * 4 + i][k];
                a[4 + i] = As[64 + ty * 4 + i][k];
            }
            float4 b0 = *(float4*)&Bs[k][tx * 4];
            float4 b1 = *(float4*)&Bs[k][64 + tx * 4];
            bb[0] = b0.x; bb[1] = b0.y; bb[2] = b0.z; bb[3] = b0.w;
            bb[4] = b1.x; bb[5] = b1.y; bb[6] = b1.z; bb[7] = b1.w;
            #pragma unroll
            for (int i = 0; i < 8; i++)
                #pragma unroll
                for (int j = 0; j < 8; j++)
                    acc[i][j] = fmaf(a[i], bb[j], acc[i][j]);
        }
        __syncthreads();
    }
    #pragma unroll
    for (int i = 0; i < 8; i++) {
        int gr = bm + ((i < 4) ? (ty * 4 + i) : (64 + ty * 4 + i - 4));
        if (gr < M) {
            #pragma unroll
            for (int jj = 0; jj < 2; jj++) {
                int gc = bn + jj * 64 + tx * 4;
                float4 v = make_float4(acc[i][jj * 4], acc[i][jj * 4 + 1],
                                       acc[i][jj * 4 + 2], acc[i][jj * 4 + 3]);
                *(float4*)(Cp + (size_t)gr * ldc + gc) = v;
            }
        }
    }
}

// ---------------------------------------------------------------------------
// M fp32 -> bf16 hi/lo (rows >= 624 zeroed)
// ---------------------------------------------------------------------------
__global__ void mconv_kernel() {
    int row = blockIdx.x, t = threadIdx.x;
    float4 v = make_float4(0.f, 0.f, 0.f, 0.f);
    if (row < 2 * NATT) v = *(const float4*)(g_M + (size_t)row * CF + t * 4);
    float x[4] = {v.x, v.y, v.z, v.w};
    unsigned short h[4], l[4];
    #pragma unroll
    for (int j = 0; j < 4; j++) {
        __nv_bfloat16 hb = __float2bfloat16(x[j]);
        float lf = x[j] - __bfloat162float(hb);
        __nv_bfloat16 lb = __float2bfloat16(lf);
        h[j] = *(unsigned short*)&hb; l[j] = *(unsigned short*)&lb;
    }
    uint2 hp, lp;
    hp.x = (uint32_t)h[0] | ((uint32_t)h[1] << 16);
    hp.y = (uint32_t)h[2] | ((uint32_t)h[3] << 16);
    lp.x = (uint32_t)l[0] | ((uint32_t)l[1] << 16);
    lp.y = (uint32_t)l[2] | ((uint32_t)l[3] << 16);
    *(uint2*)(g_Mh + (size_t)row * CF + t * 4) = hp;
    *(uint2*)(g_Ml + (size_t)row * CF + t * 4) = lp;
}

// ---------------------------------------------------------------------------
// img [b,f,r] -> bf16 hi/lo [b,r,f] + norm^2 partials
// ---------------------------------------------------------------------------
__global__ void __launch_bounds__(256)
conv_kernel(const float* __restrict__ img) {
    int fc = blockIdx.x, b = blockIdx.y;
    int f0 = fc * 32;
    __shared__ float tile[32 * 257];
    int t = threadIdx.x;
    int fr = t >> 3, q = t & 7;

    const float4* src = (const float4*)(img + ((size_t)(b * CF + f0 + fr)) * R_);
    #pragma unroll
    for (int rr = 0; rr < 8; rr++) {
        float4 v = src[rr * 8 + q];
        int r = (rr * 8 + q) * 4;
        tile[fr * 257 + r + 0] = v.x; tile[fr * 257 + r + 1] = v.y;
        tile[fr * 257 + r + 2] = v.z; tile[fr * 257 + r + 3] = v.w;
    }
    __syncthreads();

    {
        float s = 0.f;
        #pragma unroll
        for (int f = 0; f < 32; f++) { float x = tile[f * 257 + t]; s += x * x; }
        g_np[((size_t)fc * B_ + b) * R_ + t] = s;
    }

    #pragma unroll
    for (int p = 0; p < 4; p++) {
        int r = p * 64 + (t >> 2);
        int fq = t & 3;
        uint32_t hw[4], lw[4];
        #pragma unroll
        for (int u = 0; u < 4; u++) {
            float x0 = tile[(fq * 8 + u * 2 + 0) * 257 + r];
            float x1 = tile[(fq * 8 + u * 2 + 1) * 257 + r];
            __nv_bfloat16 h0 = __float2bfloat16(x0);
            __nv_bfloat16 h1 = __float2bfloat16(x1);
            __nv_bfloat16 l0 = __float2bfloat16(x0 - __bfloat162float(h0));
            __nv_bfloat16 l1 = __float2bfloat16(x1 - __bfloat162float(h1));
            hw[u] = (uint32_t)(*(unsigned short*)&h0) | ((uint32_t)(*(unsigned short*)&h1) << 16);
            lw[u] = (uint32_t)(*(unsigned short*)&l0) | ((uint32_t)(*(unsigned short*)&l1) << 16);
        }
        size_t base = ((size_t)(b * R_ + r)) * CF + f0 + fq * 8;
        *(uint4*)(g_Th + base) = make_uint4(hw[0], hw[1], hw[2], hw[3]);
        *(uint4*)(g_Tl + base) = make_uint4(lw[0], lw[1], lw[2], lw[3]);
    }
}

__global__ void reduce_norm_kernel() {
    int b = blockIdx.x, r = threadIdx.x;
    float s = 0.f;
    #pragma unroll
    for (int fc = 0; fc < 32; fc++) s += g_np[((size_t)fc * B_ + b) * R_ + r];
    g_invn[b * R_ + r] = 1.f / fmaxf(sqrtf(s), 1e-12f);
}

// ---------------------------------------------------------------------------
// Main: per (mtile,b): D[128,256] = Mtile @ imgT_b^T via mma.sync bf16 hi/lo,
// double-buffered cp.async, fused softmax-dot epilogue through smem.
// ---------------------------------------------------------------------------
__global__ void __launch_bounds__(256, 1)
main_gemm(float* __restrict__ out) {
    extern __shared__ char smem[];
    const uint32_t sb = smem_u32(smem);
    const int t = threadIdx.x;
    const int mtile = blockIdx.x;   // 0..4
    const int b = blockIdx.y;       // 0..127

    float* inv_sm = (float*)(smem + INV_OFF);
    inv_sm[t] = g_invn[b * R_ + t];

    // ---- chunk loader: 64 halves (128B) of K per chunk ----
    auto load_chunk = [&](int c, uint32_t st) {
        const int f0 = c * 64;
        #pragma unroll
        for (int i = 0; i < 4; i++) {
            int s = i * 256 + t;
            int row = s >> 3, q = s & 7;
            size_t gi = (size_t)(mtile * 128 + row) * CF + f0 + q * 8;
            uint32_t so = st + row * PITCH + q * 16;
            cp16(so + SA_H, g_Mh + gi);
            cp16(so + SA_L, g_Ml + gi);
        }
        #pragma unroll
        for (int i = 0; i < 8; i++) {
            int s = i * 256 + t;
            int row = s >> 3, q = s & 7;
            size_t gi = (size_t)(b * R_ + row) * CF + f0 + q * 8;
            uint32_t so = st + row * PITCH + q * 16;
            cp16(so + SB_H, g_Th + gi);
            cp16(so + SB_L, g_Tl + gi);
        }
    };

    load_chunk(0, sb);
    CP_COMMIT();

    const int l = t & 31, wid = t >> 5;
    const int wid_m = wid >> 1;   // 0..3 -> 32 rows each
    const int wid_n = wid & 1;    // 0..1 -> 128 cols each

    // ldmatrix per-lane relative offsets
    uint32_t a_rel[2];
    #pragma unroll
    for (int mt = 0; mt < 2; mt++)
        a_rel[mt] = (uint32_t)((wid_m * 32 + mt * 16 + (l & 15)) * PITCH + ((l >> 4) << 4));
    uint32_t b_rel[2][4];
    #pragma unroll
    for (int nh = 0; nh < 2; nh++)
        #pragma unroll
        for (int u = 0; u < 4; u++) {
            int row = wid_n * 128 + nh * 64 + u * 16 + ((l >> 4) << 3) + (l & 7);
            b_rel[nh][u] = (uint32_t)(row * PITCH + (((l >> 3) & 1) << 4));
        }

    float acc[2][16][4];
    #pragma unroll
    for (int mt = 0; mt < 2; mt++)
        #pragma unroll
        for (int nf = 0; nf < 16; nf++)
            #pragma unroll
            for (int x = 0; x < 4; x++) acc[mt][nf][x] = 0.f;

    for (int c = 0; c < 16; c++) {
        if (c < 15) { load_chunk(c + 1, sb + ((c + 1) & 1) * STAGE); CP_COMMIT(); CP_WAIT(1); }
        else CP_WAIT(0);
        __syncthreads();
        const uint32_t st = sb + (c & 1) * STAGE;

        #pragma unroll
        for (int j = 0; j < 4; j++) {          // 4 k16 steps per chunk
            uint32_t ah[2][4], al[2][4];
            #pragma unroll
            for (int mt = 0; mt < 2; mt++) {
                ldsm4(ah[mt][0], ah[mt][1], ah[mt][2], ah[mt][3],
                      st + SA_H + a_rel[mt] + j * 32);
                ldsm4(al[mt][0], al[mt][1], al[mt][2], al[mt][3],
                      st + SA_L + a_rel[mt] + j * 32);
            }
            #pragma unroll
            for (int nh = 0; nh < 2; nh++) {
                uint32_t bh[16], bl[16];
                #pragma unroll
                for (int u = 0; u < 4; u++) {
                    ldsm4(bh[4 * u], bh[4 * u + 1], bh[4 * u + 2], bh[4 * u + 3],
                          st + SB_H + b_rel[nh][u] + j * 32);
                    ldsm4(bl[4 * u], bl[4 * u + 1], bl[4 * u + 2], bl[4 * u + 3],
                          st + SB_L + b_rel[nh][u] + j * 32);
                }
                #pragma unroll
                for (int f = 0; f < 8; f++) {
                    int nf = nh * 8 + f;
                    const uint32_t* pbh = &bh[(f >> 1) * 4 + (f & 1) * 2];
                    const uint32_t* pbl = &bl[(f >> 1) * 4 + (f & 1) * 2];
                    #pragma unroll
                    for (int mt = 0; mt < 2; mt++) {
                        mma16816(acc[mt][nf], ah[mt], pbh);   // hi*hi
                        mma16816(acc[mt][nf], ah[mt], pbl);   // hi*lo
                        mma16816(acc[mt][nf], al[mt], pbh);   // lo*hi
                    }
                }
            }
        }
        __syncthreads();
    }

    // ---- epilogue: stage C in smem, per-row softmax-dot on Q/P pairs ----
    float* Cs = (float*)smem;
    const int g = l >> 2, tig = l & 3;
    #pragma unroll
    for (int mt = 0; mt < 2; mt++)
        #pragma unroll
        for (int nf = 0; nf < 16; nf++) {
            int row = wid_m * 32 + mt * 16 + g;
            int col = wid_n * 128 + nf * 8 + tig * 2;
            Cs[row * CPITCH + col]           = acc[mt][nf][0];
            Cs[row * CPITCH + col + 1]       = acc[mt][nf][1];
            Cs[(row + 8) * CPITCH + col]     = acc[mt][nf][2];
            Cs[(row + 8) * CPITCH + col + 1] = acc[mt][nf][3];
        }
    __syncthreads();

    if (t < 128) {
        float s = 0.f, d = 0.f;
        const int odd = t & 1;
        #pragma unroll 8
        for (int j = 0; j < 256; j++) {
            float va = Cs[t * CPITCH + j] * inv_sm[j];
            float pv = __shfl_xor_sync(0xffffffffu, va, 1);
            float lg = odd ? pv : va;
            float vl = odd ? va : pv;
            float e = __expf(lg);
            s += e;
            d += e * vl;
        }
        if (!odd) {
            int i = (mtile * 128 + t) >> 1;
            if (i < NATT) out[b * NATT + i] = d / s;
        }
    }
}

// ---------------------------------------------------------------------------
extern "C" void kernel_launch(void* const* d_in, const int* in_sizes, int n_in,
                              void* d_out, int out_size) {
    const float* img = (const float*)d_in[0];
    const float* V   = (const float*)d_in[1];
    const float* W1  = (const float*)d_in[2];
    const float* W2  = (const float*)d_in[3];
    float* out = (float*)d_out;

    cudaFuncSetAttribute(main_gemm, cudaFuncAttributeMaxDynamicSharedMemorySize,
                         SMEM_TOTAL);

    vv_kernel<<<NATT, 256>>>(V);
    gemm_small<<<dim3(3, 8, 2), 256>>>(W1, W2);
    mconv_kernel<<<NJP, 256>>>();
    conv_kernel<<<dim3(32, B_), 256>>>(img);
    reduce_norm_kernel<<<B_, 256>>>();
    main_gemm<<<dim3(5, B_), 256, SMEM_TOTAL>>>(out);
}

// round 12
// speedup vs baseline: 3.3773x; 1.4559x over previous
#include <cuda_runtime.h>
#include <cuda_fp16.h>
#include <math.h>
#include <stdint.h>

#define B_   128
#define CF   1024
#define R_   256
#define NATT 312
#define DV   300
#define NJP  640   // padded interleaved rows (row 2i=Q_i, 2i+1=P_i)

// ---------------- device scratch ----------------
__device__ float g_vv[NATT * DV];
__device__ float g_M[NJP * CF];                  // fp32 interleaved Q/P
__device__ __half g_Mh[NJP * CF];                // fp16 hi of M
__device__ __half g_Ml[NJP * CF];                // fp16 lo of M
__device__ __half g_T[(size_t)B_ * R_ * CF];     // img^T fp16 [b][r][f]
__device__ float g_np[32 * B_ * R_];
__device__ float g_invn[B_ * R_];

// ---------------- smem layout (main kernel) ----------------
#define PITCH  144          // 128B data + 16B pad: conflict-free LDSM
#define SA_H   0            // 128 rows * 144
#define SA_L   18432
#define SB     36864        // 256 rows * 144
#define STAGE  73728
#define INV_OFF (3 * STAGE)               // 221184
#define SMEM_TOTAL (INV_OFF + 1024)       // 222208
#define CPITCH 257                        // epilogue fp32 C pitch (floats)

// ---------------- PTX helpers (plain sm_80+ PTX only) ----------------
__device__ __forceinline__ uint32_t smem_u32(const void* p) {
    uint32_t a;
    asm("{ .reg .u64 t; cvta.to.shared.u64 t, %1; cvt.u32.u64 %0, t; }" : "=r"(a) : "l"(p));
    return a;
}
__device__ __forceinline__ void cp16(uint32_t dst, const void* src) {
    asm volatile("cp.async.cg.shared.global [%0], [%1], 16;" :: "r"(dst), "l"(src));
}
#define CP_COMMIT() asm volatile("cp.async.commit_group;" ::: "memory")
#define CP_WAIT(n)  asm volatile("cp.async.wait_group %0;" :: "n"(n) : "memory")

__device__ __forceinline__ void ldsm4(uint32_t& r0, uint32_t& r1, uint32_t& r2,
                                      uint32_t& r3, uint32_t addr) {
    asm volatile("ldmatrix.sync.aligned.m8n8.x4.shared.b16 {%0,%1,%2,%3}, [%4];"
                 : "=r"(r0), "=r"(r1), "=r"(r2), "=r"(r3) : "r"(addr));
}
__device__ __forceinline__ void mma16816(float* d, const uint32_t* a, const uint32_t* b) {
    asm volatile("mma.sync.aligned.m16n8k16.row.col.f32.f16.f16.f32 "
                 "{%0,%1,%2,%3}, {%4,%5,%6,%7}, {%8,%9}, {%0,%1,%2,%3};"
                 : "+f"(d[0]), "+f"(d[1]), "+f"(d[2]), "+f"(d[3])
                 : "r"(a[0]), "r"(a[1]), "r"(a[2]), "r"(a[3]), "r"(b[0]), "r"(b[1]));
}

// ---------------------------------------------------------------------------
// vv = V / max(||row||, eps)
// ---------------------------------------------------------------------------
__global__ void vv_kernel(const float* __restrict__ V) {
    int i = blockIdx.x, tid = threadIdx.x;
    __shared__ float red[8];
    float s = 0.f;
    for (int v = tid; v < DV; v += 256) { float x = V[i * DV + v]; s += x * x; }
    #pragma unroll
    for (int o = 16; o; o >>= 1) s += __shfl_xor_sync(0xffffffffu, s, o);
    if ((tid & 31) == 0) red[tid >> 5] = s;
    __syncthreads();
    if (tid == 0) { float t = 0.f; for (int w = 0; w < 8; w++) t += red[w]; red[0] = t; }
    __syncthreads();
    float inv = 1.f / fmaxf(sqrtf(red[0]), 1e-12f);
    for (int v = tid; v < DV; v += 256) g_vv[i * DV + v] = V[i * DV + v] * inv;
}

// ---------------------------------------------------------------------------
// Small GEMMs, 64x128 tiles: z=0: Q=vv@W1 -> even rows; z=1: P=vv@W2 -> odd
// ---------------------------------------------------------------------------
__global__ void __launch_bounds__(256)
gemm_small(const float* __restrict__ W1, const float* __restrict__ W2) {
    const int bm = blockIdx.x * 64;
    const int bn = blockIdx.y * 128;
    const int z = blockIdx.z;
    const float* A = g_vv;
    const float* Bp = z ? W2 : W1;
    float* Cp = g_M + z * CF;
    const int M = NATT, K = DV, lda = DV, ldb = CF, ldc = 2 * CF;

    __shared__ float As[64][17];
    __shared__ float Bs[16][128];
    const int tid = threadIdx.x;
    const int tx = tid & 15, ty = tid >> 4;
    float acc[4][8];
    #pragma unroll
    for (int i = 0; i < 4; i++)
        #pragma unroll
        for (int j = 0; j < 8; j++) acc[i][j] = 0.f;

    for (int k0 = 0; k0 < K; k0 += 16) {
        {   // A tile: 64x16 = 256 float4, one per thread
            int row = tid >> 2, kk4 = (tid & 3) * 4;
            float4 v = make_float4(0.f, 0.f, 0.f, 0.f);
            int gr = bm + row, gk = k0 + kk4;
            if (gr < M) {
                if (gk + 3 < K) v = *(const float4*)(A + (size_t)gr * lda + gk);
                else {
                    float t0 = (gk + 0 < K) ? A[(size_t)gr * lda + gk + 0] : 0.f;
                    float t1 = (gk + 1 < K) ? A[(size_t)gr * lda + gk + 1] : 0.f;
                    float t2 = (gk + 2 < K) ? A[(size_t)gr * lda + gk + 2] : 0.f;
                    float t3 = (gk + 3 < K) ? A[(size_t)gr * lda + gk + 3] : 0.f;
                    v = make_float4(t0, t1, t2, t3);
                }
            }
            As[row][kk4 + 0] = v.x; As[row][kk4 + 1] = v.y;
            As[row][kk4 + 2] = v.z; As[row][kk4 + 3] = v.w;
        }
        #pragma unroll
        for (int it = 0; it < 2; it++) {
            int s = it * 256 + tid;
            int kk = s >> 5, n4 = (s & 31) * 4;
            float4 v = make_float4(0.f, 0.f, 0.f, 0.f);
            int gk = k0 + kk;
            if (gk < K) v = *(const float4*)(Bp + (size_t)gk * ldb + bn + n4);
            *(float4*)&Bs[kk][n4] = v;
        }
        __syncthreads();
        #pragma unroll
        for (int k = 0; k < 16; k++) {
            float a[4], bb[8];
            #pragma unroll
            for (int i = 0; i < 4; i++) a[i] = As[ty * 4 + i][k];
            float4 b0 = *(float4*)&Bs[k][tx * 4];
            float4 b1 = *(float4*)&Bs[k][64 + tx * 4];
            bb[0] = b0.x; bb[1] = b0.y; bb[2] = b0.z; bb[3] = b0.w;
            bb[4] = b1.x; bb[5] = b1.y; bb[6] = b1.z; bb[7] = b1.w;
            #pragma unroll
            for (int i = 0; i < 4; i++)
                #pragma unroll
                for (int j = 0; j < 8; j++)
                    acc[i][j] = fmaf(a[i], bb[j], acc[i][j]);
        }
        __syncthreads();
    }
    #pragma unroll
    for (int i = 0; i < 4; i++) {
        int gr = bm + ty * 4 + i;
        if (gr < M) {
            #pragma unroll
            for (int jj = 0; jj < 2; jj++) {
                int gc = bn + jj * 64 + tx * 4;
                float4 v = make_float4(acc[i][jj * 4], acc[i][jj * 4 + 1],
                                       acc[i][jj * 4 + 2], acc[i][jj * 4 + 3]);
                *(float4*)(Cp + (size_t)gr * ldc + gc) = v;
            }
        }
    }
}

// ---------------------------------------------------------------------------
// M fp32 -> fp16 hi/lo (rows >= 624 zeroed)
// ---------------------------------------------------------------------------
__global__ void mconv_kernel() {
    int row = blockIdx.x, t = threadIdx.x;
    float4 v = make_float4(0.f, 0.f, 0.f, 0.f);
    if (row < 2 * NATT) v = *(const float4*)(g_M + (size_t)row * CF + t * 4);
    float x[4] = {v.x, v.y, v.z, v.w};
    unsigned short h[4], l[4];
    #pragma unroll
    for (int j = 0; j < 4; j++) {
        __half hb = __float2half(x[j]);
        __half lb = __float2half(x[j] - __half2float(hb));
        h[j] = *(unsigned short*)&hb; l[j] = *(unsigned short*)&lb;
    }
    uint2 hp, lp;
    hp.x = (uint32_t)h[0] | ((uint32_t)h[1] << 16);
    hp.y = (uint32_t)h[2] | ((uint32_t)h[3] << 16);
    lp.x = (uint32_t)l[0] | ((uint32_t)l[1] << 16);
    lp.y = (uint32_t)l[2] | ((uint32_t)l[3] << 16);
    *(uint2*)(g_Mh + (size_t)row * CF + t * 4) = hp;
    *(uint2*)(g_Ml + (size_t)row * CF + t * 4) = lp;
}

// ---------------------------------------------------------------------------
// img [b,f,r] -> fp16 [b,r,f] + norm^2 partials
// ---------------------------------------------------------------------------
__global__ void __launch_bounds__(256)
conv_kernel(const float* __restrict__ img) {
    int fc = blockIdx.x, b = blockIdx.y;
    int f0 = fc * 32;
    __shared__ float tile[32 * 257];
    int t = threadIdx.x;
    int fr = t >> 3, q = t & 7;

    const float4* src = (const float4*)(img + ((size_t)(b * CF + f0 + fr)) * R_);
    #pragma unroll
    for (int rr = 0; rr < 8; rr++) {
        float4 v = src[rr * 8 + q];
        int r = (rr * 8 + q) * 4;
        tile[fr * 257 + r + 0] = v.x; tile[fr * 257 + r + 1] = v.y;
        tile[fr * 257 + r + 2] = v.z; tile[fr * 257 + r + 3] = v.w;
    }
    __syncthreads();

    {
        float s = 0.f;
        #pragma unroll
        for (int f = 0; f < 32; f++) { float x = tile[f * 257 + t]; s += x * x; }
        g_np[((size_t)fc * B_ + b) * R_ + t] = s;
    }

    #pragma unroll
    for (int p = 0; p < 4; p++) {
        int r = p * 64 + (t >> 2);
        int fq = t & 3;
        uint32_t hw[4];
        #pragma unroll
        for (int u = 0; u < 4; u++) {
            float x0 = tile[(fq * 8 + u * 2 + 0) * 257 + r];
            float x1 = tile[(fq * 8 + u * 2 + 1) * 257 + r];
            __half h0 = __float2half(x0);
            __half h1 = __float2half(x1);
            hw[u] = (uint32_t)(*(unsigned short*)&h0) | ((uint32_t)(*(unsigned short*)&h1) << 16);
        }
        size_t base = ((size_t)(b * R_ + r)) * CF + f0 + fq * 8;
        *(uint4*)(g_T + base) = make_uint4(hw[0], hw[1], hw[2], hw[3]);
    }
}

__global__ void reduce_norm_kernel() {
    int b = blockIdx.x, r = threadIdx.x;
    float s = 0.f;
    #pragma unroll
    for (int fc = 0; fc < 32; fc++) s += g_np[((size_t)fc * B_ + b) * R_ + r];
    g_invn[b * R_ + r] = 1.f / fmaxf(sqrtf(s), 1e-12f);
}

// ---------------------------------------------------------------------------
// Main: per (mtile,b): D[128,256] = (Ah+Al) @ T_b^T, 2-product fp16 mma,
// 3-stage cp.async pipeline, fused softmax-dot epilogue.
// ---------------------------------------------------------------------------
__global__ void __launch_bounds__(256, 1)
main_gemm(float* __restrict__ out) {
    extern __shared__ char smem[];
    const uint32_t sb = smem_u32(smem);
    const int t = threadIdx.x;
    const int mtile = blockIdx.x;   // 0..4
    const int b = blockIdx.y;       // 0..127

    float* inv_sm = (float*)(smem + INV_OFF);
    inv_sm[t] = g_invn[b * R_ + t];

    auto load_chunk = [&](int c, uint32_t st) {
        const int f0 = c * 64;
        #pragma unroll
        for (int i = 0; i < 4; i++) {
            int s = i * 256 + t;
            int row = s >> 3, q = s & 7;
            size_t gi = (size_t)(mtile * 128 + row) * CF + f0 + q * 8;
            uint32_t so = st + row * PITCH + q * 16;
            cp16(so + SA_H, g_Mh + gi);
            cp16(so + SA_L, g_Ml + gi);
        }
        #pragma unroll
        for (int i = 0; i < 8; i++) {
            int s = i * 256 + t;
            int row = s >> 3, q = s & 7;
            size_t gi = (size_t)(b * R_ + row) * CF + f0 + q * 8;
            cp16(st + SB + row * PITCH + q * 16, g_T + gi);
        }
    };

    load_chunk(0, sb);
    CP_COMMIT();
    load_chunk(1, sb + STAGE);
    CP_COMMIT();

    const int l = t & 31, wid = t >> 5;
    const int wid_m = wid >> 1;   // 0..3 -> 32 rows each
    const int wid_n = wid & 1;    // 0..1 -> 128 cols each

    uint32_t a_rel[2];
    #pragma unroll
    for (int mt = 0; mt < 2; mt++)
        a_rel[mt] = (uint32_t)((wid_m * 32 + mt * 16 + (l & 15)) * PITCH + ((l >> 4) << 4));
    uint32_t b_rel[2][4];
    #pragma unroll
    for (int nh = 0; nh < 2; nh++)
        #pragma unroll
        for (int u = 0; u < 4; u++) {
            int row = wid_n * 128 + nh * 64 + u * 16 + ((l >> 4) << 3) + (l & 7);
            b_rel[nh][u] = (uint32_t)(row * PITCH + (((l >> 3) & 1) << 4));
        }

    float acc[2][16][4];
    #pragma unroll
    for (int mt = 0; mt < 2; mt++)
        #pragma unroll
        for (int nf = 0; nf < 16; nf++)
            #pragma unroll
            for (int x = 0; x < 4; x++) acc[mt][nf][x] = 0.f;

    for (int c = 0; c < 16; c++) {
        if (c == 15) CP_WAIT(0); else CP_WAIT(1);
        __syncthreads();
        const uint32_t st = sb + (uint32_t)(c % 3) * STAGE;

        #pragma unroll
        for (int j = 0; j < 4; j++) {          // 4 k16 steps per chunk
            uint32_t ah[2][4], al[2][4];
            #pragma unroll
            for (int mt = 0; mt < 2; mt++) {
                ldsm4(ah[mt][0], ah[mt][1], ah[mt][2], ah[mt][3],
                      st + SA_H + a_rel[mt] + j * 32);
                ldsm4(al[mt][0], al[mt][1], al[mt][2], al[mt][3],
                      st + SA_L + a_rel[mt] + j * 32);
            }
            #pragma unroll
            for (int nh = 0; nh < 2; nh++) {
                uint32_t bh[16];
                #pragma unroll
                for (int u = 0; u < 4; u++)
                    ldsm4(bh[4 * u], bh[4 * u + 1], bh[4 * u + 2], bh[4 * u + 3],
                          st + SB + b_rel[nh][u] + j * 32);
                #pragma unroll
                for (int f = 0; f < 8; f++) {
                    int nf = nh * 8 + f;
                    const uint32_t* pbh = &bh[(f >> 1) * 4 + (f & 1) * 2];
                    #pragma unroll
                    for (int mt = 0; mt < 2; mt++) {
                        mma16816(acc[mt][nf], ah[mt], pbh);   // hi * B
                        mma16816(acc[mt][nf], al[mt], pbh);   // lo * B
                    }
                }
            }
        }
        if (c + 2 < 16) {
            load_chunk(c + 2, sb + (uint32_t)((c + 2) % 3) * STAGE);
            CP_COMMIT();
        }
    }
    __syncthreads();

    // ---- epilogue: stage C in smem, per-row softmax-dot on Q/P pairs ----
    float* Cs = (float*)smem;
    const int g = l >> 2, tig = l & 3;
    #pragma unroll
    for (int mt = 0; mt < 2; mt++)
        #pragma unroll
        for (int nf = 0; nf < 16; nf++) {
            int row = wid_m * 32 + mt * 16 + g;
            int col = wid_n * 128 + nf * 8 + tig * 2;
            Cs[row * CPITCH + col]           = acc[mt][nf][0];
            Cs[row * CPITCH + col + 1]       = acc[mt][nf][1];
            Cs[(row + 8) * CPITCH + col]     = acc[mt][nf][2];
            Cs[(row + 8) * CPITCH + col + 1] = acc[mt][nf][3];
        }
    __syncthreads();

    if (t < 128) {
        float s = 0.f, d = 0.f;
        const int odd = t & 1;
        #pragma unroll 8
        for (int j = 0; j < 256; j++) {
            float va = Cs[t * CPITCH + j] * inv_sm[j];
            float pv = __shfl_xor_sync(0xffffffffu, va, 1);
            float lg = odd ? pv : va;
            float vl = odd ? va : pv;
            float e = __expf(lg);
            s += e;
            d += e * vl;
        }
        if (!odd) {
            int i = (mtile * 128 + t) >> 1;
            if (i < NATT) out[b * NATT + i] = d / s;
        }
    }
}

// ---------------------------------------------------------------------------
extern "C" void kernel_launch(void* const* d_in, const int* in_sizes, int n_in,
                              void* d_out, int out_size) {
    const float* img = (const float*)d_in[0];
    const float* V   = (const float*)d_in[1];
    const float* W1  = (const float*)d_in[2];
    const float* W2  = (const float*)d_in[3];
    float* out = (float*)d_out;

    cudaFuncSetAttribute(main_gemm, cudaFuncAttributeMaxDynamicSharedMemorySize,
                         SMEM_TOTAL);

    vv_kernel<<<NATT, 256>>>(V);
    gemm_small<<<dim3(5, 8, 2), 256>>>(W1, W2);
    mconv_kernel<<<NJP, 256>>>();
    conv_kernel<<<dim3(32, B_), 256>>>(img);
    reduce_norm_kernel<<<B_, 256>>>();
    main_gemm<<<dim3(5, B_), 256, SMEM_TOTAL>>>(out);
}

// round 15
// speedup vs baseline: 4.5447x; 1.3457x over previous
#include <cuda_runtime.h>
#include <cuda_fp16.h>
#include <math.h>
#include <stdint.h>

#define B_   128
#define CF   1024
#define R_   256
#define NATT 312
#define DV   300
#define NJP  640   // padded interleaved rows (row 2i=Q_i, 2i+1=P_i)

// ---------------- device scratch ----------------
__device__ float g_vv[NATT * DV];
__device__ __half g_Mh[NJP * CF];                // fp16 M, interleaved Q/P (pad rows stay 0)
__device__ __half g_T[(size_t)B_ * R_ * CF];     // img^T fp16 [b][r][f]
__device__ float g_np[32 * B_ * R_];
__device__ float g_invn[B_ * R_];

// ---------------- smem layout (main kernel) ----------------
#define PITCH  144          // 128B data + 16B pad: conflict-free LDSM
#define SA     0            // 128 rows * 144 = 18432
#define SB     18432        // 256 rows * 144 = 36864
#define STAGE  55296
#define NSTG   4
#define INV_OFF (NSTG * STAGE)            // 221184
#define SMEM_TOTAL (INV_OFF + 1024)       // 222208
#define CPITCH 257                        // epilogue fp32 C pitch (floats)

// ---------------- PTX helpers (plain sm_80+ PTX only) ----------------
__device__ __forceinline__ uint32_t smem_u32(const void* p) {
    uint32_t a;
    asm("{ .reg .u64 t; cvta.to.shared.u64 t, %1; cvt.u32.u64 %0, t; }" : "=r"(a) : "l"(p));
    return a;
}
__device__ __forceinline__ void cp16(uint32_t dst, const void* src) {
    asm volatile("cp.async.cg.shared.global [%0], [%1], 16;" :: "r"(dst), "l"(src));
}
#define CP_COMMIT() asm volatile("cp.async.commit_group;" ::: "memory")
#define CP_WAIT(n)  asm volatile("cp.async.wait_group %0;" :: "n"(n) : "memory")

__device__ __forceinline__ void ldsm4(uint32_t& r0, uint32_t& r1, uint32_t& r2,
                                      uint32_t& r3, uint32_t addr) {
    asm volatile("ldmatrix.sync.aligned.m8n8.x4.shared.b16 {%0,%1,%2,%3}, [%4];"
                 : "=r"(r0), "=r"(r1), "=r"(r2), "=r"(r3) : "r"(addr));
}
__device__ __forceinline__ void mma16816(float* d, const uint32_t* a, const uint32_t* b) {
    asm volatile("mma.sync.aligned.m16n8k16.row.col.f32.f16.f16.f32 "
                 "{%0,%1,%2,%3}, {%4,%5,%6,%7}, {%8,%9}, {%0,%1,%2,%3};"
                 : "+f"(d[0]), "+f"(d[1]), "+f"(d[2]), "+f"(d[3])
                 : "r"(a[0]), "r"(a[1]), "r"(a[2]), "r"(a[3]), "r"(b[0]), "r"(b[1]));
}

// ---------------------------------------------------------------------------
// vv = V / max(||row||, eps)
// ---------------------------------------------------------------------------
__global__ void vv_kernel(const float* __restrict__ V) {
    int i = blockIdx.x, tid = threadIdx.x;
    __shared__ float red[8];
    float s = 0.f;
    for (int v = tid; v < DV; v += 256) { float x = V[i * DV + v]; s += x * x; }
    #pragma unroll
    for (int o = 16; o; o >>= 1) s += __shfl_xor_sync(0xffffffffu, s, o);
    if ((tid & 31) == 0) red[tid >> 5] = s;
    __syncthreads();
    if (tid == 0) { float t = 0.f; for (int w = 0; w < 8; w++) t += red[w]; red[0] = t; }
    __syncthreads();
    float inv = 1.f / fmaxf(sqrtf(red[0]), 1e-12f);
    for (int v = tid; v < DV; v += 256) g_vv[i * DV + v] = V[i * DV + v] * inv;
}

// ---------------------------------------------------------------------------
// Small GEMMs, 64x128 tiles: z=0: Q=vv@W1 -> even rows; z=1: P=vv@W2 -> odd
// Writes fp16 directly into interleaved g_Mh.
// ---------------------------------------------------------------------------
__global__ void __launch_bounds__(256)
gemm_small(const float* __restrict__ W1, const float* __restrict__ W2) {
    const int bm = blockIdx.x * 64;
    const int bn = blockIdx.y * 128;
    const int z = blockIdx.z;
    const float* A = g_vv;
    const float* Bp = z ? W2 : W1;
    const int M = NATT, K = DV, lda = DV, ldb = CF;

    __shared__ float As[64][17];
    __shared__ float Bs[16][128];
    const int tid = threadIdx.x;
    const int tx = tid & 15, ty = tid >> 4;
    float acc[4][8];
    #pragma unroll
    for (int i = 0; i < 4; i++)
        #pragma unroll
        for (int j = 0; j < 8; j++) acc[i][j] = 0.f;

    for (int k0 = 0; k0 < K; k0 += 16) {
        {   // A tile: 64x16 = 256 float4, one per thread
            int row = tid >> 2, kk4 = (tid & 3) * 4;
            float4 v = make_float4(0.f, 0.f, 0.f, 0.f);
            int gr = bm + row, gk = k0 + kk4;
            if (gr < M) {
                if (gk + 3 < K) v = *(const float4*)(A + (size_t)gr * lda + gk);
                else {
                    float t0 = (gk + 0 < K) ? A[(size_t)gr * lda + gk + 0] : 0.f;
                    float t1 = (gk + 1 < K) ? A[(size_t)gr * lda + gk + 1] : 0.f;
                    float t2 = (gk + 2 < K) ? A[(size_t)gr * lda + gk + 2] : 0.f;
                    float t3 = (gk + 3 < K) ? A[(size_t)gr * lda + gk + 3] : 0.f;
                    v = make_float4(t0, t1, t2, t3);
                }
            }
            As[row][kk4 + 0] = v.x; As[row][kk4 + 1] = v.y;
            As[row][kk4 + 2] = v.z; As[row][kk4 + 3] = v.w;
        }
        #pragma unroll
        for (int it = 0; it < 2; it++) {
            int s = it * 256 + tid;
            int kk = s >> 5, n4 = (s & 31) * 4;
            float4 v = make_float4(0.f, 0.f, 0.f, 0.f);
            int gk = k0 + kk;
            if (gk < K) v = *(const float4*)(Bp + (size_t)gk * ldb + bn + n4);
            *(float4*)&Bs[kk][n4] = v;
        }
        __syncthreads();
        #pragma unroll
        for (int k = 0; k < 16; k++) {
            float a[4], bb[8];
            #pragma unroll
            for (int i = 0; i < 4; i++) a[i] = As[ty * 4 + i][k];
            float4 b0 = *(float4*)&Bs[k][tx * 4];
            float4 b1 = *(float4*)&Bs[k][64 + tx * 4];
            bb[0] = b0.x; bb[1] = b0.y; bb[2] = b0.z; bb[3] = b0.w;
            bb[4] = b1.x; bb[5] = b1.y; bb[6] = b1.z; bb[7] = b1.w;
            #pragma unroll
            for (int i = 0; i < 4; i++)
                #pragma unroll
                for (int j = 0; j < 8; j++)
                    acc[i][j] = fmaf(a[i], bb[j], acc[i][j]);
        }
        __syncthreads();
    }
    #pragma unroll
    for (int i = 0; i < 4; i++) {
        int gr = bm + ty * 4 + i;
        if (gr < M) {
            int row = 2 * gr + z;   // interleaved
            #pragma unroll
            for (int jj = 0; jj < 2; jj++) {
                int gc = bn + jj * 64 + tx * 4;
                unsigned short h[4];
                #pragma unroll
                for (int u = 0; u < 4; u++) {
                    __half hv = __float2half(acc[i][jj * 4 + u]);
                    h[u] = *(unsigned short*)&hv;
                }
                uint2 pk;
                pk.x = (uint32_t)h[0] | ((uint32_t)h[1] << 16);
                pk.y = (uint32_t)h[2] | ((uint32_t)h[3] << 16);
                *(uint2*)(g_Mh + (size_t)row * CF + gc) = pk;
            }
        }
    }
}

// ---------------------------------------------------------------------------
// img [b,f,r] -> fp16 [b,r,f] + norm^2 partials
// ---------------------------------------------------------------------------
__global__ void __launch_bounds__(256)
conv_kernel(const float* __restrict__ img) {
    int fc = blockIdx.x, b = blockIdx.y;
    int f0 = fc * 32;
    __shared__ float tile[32 * 257];
    int t = threadIdx.x;
    int fr = t >> 3, q = t & 7;

    const float4* src = (const float4*)(img + ((size_t)(b * CF + f0 + fr)) * R_);
    #pragma unroll
    for (int rr = 0; rr < 8; rr++) {
        float4 v = src[rr * 8 + q];
        int r = (rr * 8 + q) * 4;
        tile[fr * 257 + r + 0] = v.x; tile[fr * 257 + r + 1] = v.y;
        tile[fr * 257 + r + 2] = v.z; tile[fr * 257 + r + 3] = v.w;
    }
    __syncthreads();

    {
        float s = 0.f;
        #pragma unroll
        for (int f = 0; f < 32; f++) { float x = tile[f * 257 + t]; s += x * x; }
        g_np[((size_t)fc * B_ + b) * R_ + t] = s;
    }

    #pragma unroll
    for (int p = 0; p < 4; p++) {
        int r = p * 64 + (t >> 2);
        int fq = t & 3;
        uint32_t hw[4];
        #pragma unroll
        for (int u = 0; u < 4; u++) {
            float x0 = tile[(fq * 8 + u * 2 + 0) * 257 + r];
            float x1 = tile[(fq * 8 + u * 2 + 1) * 257 + r];
            __half h0 = __float2half(x0);
            __half h1 = __float2half(x1);
            hw[u] = (uint32_t)(*(unsigned short*)&h0) | ((uint32_t)(*(unsigned short*)&h1) << 16);
        }
        size_t base = ((size_t)(b * R_ + r)) * CF + f0 + fq * 8;
        *(uint4*)(g_T + base) = make_uint4(hw[0], hw[1], hw[2], hw[3]);
    }
}

__global__ void reduce_norm_kernel() {
    int b = blockIdx.x, r = threadIdx.x;
    float s = 0.f;
    #pragma unroll
    for (int fc = 0; fc < 32; fc++) s += g_np[((size_t)fc * B_ + b) * R_ + r];
    g_invn[b * R_ + r] = 1.f / fmaxf(sqrtf(s), 1e-12f);
}

// ---------------------------------------------------------------------------
// Main: per (mtile,b): D[128,256] = A @ T_b^T, single-product fp16 mma,
// 4-stage cp.async pipeline, fused softmax-dot epilogue.
// ---------------------------------------------------------------------------
__global__ void __launch_bounds__(256, 1)
main_gemm(float* __restrict__ out) {
    extern __shared__ char smem[];
    const uint32_t sb = smem_u32(smem);
    const int t = threadIdx.x;
    const int mtile = blockIdx.x;   // 0..4
    const int b = blockIdx.y;       // 0..127

    float* inv_sm = (float*)(smem + INV_OFF);
    inv_sm[t] = g_invn[b * R_ + t];

    auto load_chunk = [&](int c, uint32_t st) {
        const int f0 = c * 64;
        #pragma unroll
        for (int i = 0; i < 4; i++) {
            int s = i * 256 + t;
            int row = s >> 3, q = s & 7;
            size_t gi = (size_t)(mtile * 128 + row) * CF + f0 + q * 8;
            cp16(st + SA + row * PITCH + q * 16, g_Mh + gi);
        }
        #pragma unroll
        for (int i = 0; i < 8; i++) {
            int s = i * 256 + t;
            int row = s >> 3, q = s & 7;
            size_t gi = (size_t)(b * R_ + row) * CF + f0 + q * 8;
            cp16(st + SB + row * PITCH + q * 16, g_T + gi);
        }
    };

    load_chunk(0, sb);
    CP_COMMIT();
    load_chunk(1, sb + STAGE);
    CP_COMMIT();
    load_chunk(2, sb + 2 * STAGE);
    CP_COMMIT();

    const int l = t & 31, wid = t >> 5;
    const int wid_m = wid >> 1;   // 0..3 -> 32 rows each
    const int wid_n = wid & 1;    // 0..1 -> 128 cols each

    uint32_t a_rel[2];
    #pragma unroll
    for (int mt = 0; mt < 2; mt++)
        a_rel[mt] = (uint32_t)((wid_m * 32 + mt * 16 + (l & 15)) * PITCH + ((l >> 4) << 4));
    uint32_t b_rel[2][4];
    #pragma unroll
    for (int nh = 0; nh < 2; nh++)
        #pragma unroll
        for (int u = 0; u < 4; u++) {
            int row = wid_n * 128 + nh * 64 + u * 16 + ((l >> 4) << 3) + (l & 7);
            b_rel[nh][u] = (uint32_t)(row * PITCH + (((l >> 3) & 1) << 4));
        }

    float acc[2][16][4];
    #pragma unroll
    for (int mt = 0; mt < 2; mt++)
        #pragma unroll
        for (int nf = 0; nf < 16; nf++)
            #pragma unroll
            for (int x = 0; x < 4; x++) acc[mt][nf][x] = 0.f;

    for (int c = 0; c < 16; c++) {
        if (c < 14) CP_WAIT(2);
        else if (c == 14) CP_WAIT(1);
        else CP_WAIT(0);
        __syncthreads();
        const uint32_t st = sb + (uint32_t)(c % NSTG) * STAGE;

        #pragma unroll
        for (int j = 0; j < 4; j++) {          // 4 k16 steps per chunk
            uint32_t ah[2][4];
            #pragma unroll
            for (int mt = 0; mt < 2; mt++)
                ldsm4(ah[mt][0], ah[mt][1], ah[mt][2], ah[mt][3],
                      st + SA + a_rel[mt] + j * 32);
            #pragma unroll
            for (int nh = 0; nh < 2; nh++) {
                uint32_t bh[16];
                #pragma unroll
                for (int u = 0; u < 4; u++)
                    ldsm4(bh[4 * u], bh[4 * u + 1], bh[4 * u + 2], bh[4 * u + 3],
                          st + SB + b_rel[nh][u] + j * 32);
                #pragma unroll
                for (int f = 0; f < 8; f++) {
                    int nf = nh * 8 + f;
                    const uint32_t* pbh = &bh[(f >> 1) * 4 + (f & 1) * 2];
                    #pragma unroll
                    for (int mt = 0; mt < 2; mt++)
                        mma16816(acc[mt][nf], ah[mt], pbh);
                }
            }
        }
        if (c + 3 < 16) {
            load_chunk(c + 3, sb + (uint32_t)((c + 3) % NSTG) * STAGE);
            CP_COMMIT();
        }
    }
    __syncthreads();

    // ---- epilogue: stage C in smem, per-row softmax-dot on Q/P pairs ----
    float* Cs = (float*)smem;
    const int g = l >> 2, tig = l & 3;
    #pragma unroll
    for (int mt = 0; mt < 2; mt++)
        #pragma unroll
        for (int nf = 0; nf < 16; nf++) {
            int row = wid_m * 32 + mt * 16 + g;
            int col = wid_n * 128 + nf * 8 + tig * 2;
            Cs[row * CPITCH + col]           = acc[mt][nf][0];
            Cs[row * CPITCH + col + 1]       = acc[mt][nf][1];
            Cs[(row + 8) * CPITCH + col]     = acc[mt][nf][2];
            Cs[(row + 8) * CPITCH + col + 1] = acc[mt][nf][3];
        }
    __syncthreads();

    if (t < 128) {
        float s = 0.f, d = 0.f;
        const int odd = t & 1;
        #pragma unroll 8
        for (int j = 0; j < 256; j++) {
            float va = Cs[t * CPITCH + j] * inv_sm[j];
            float pv = __shfl_xor_sync(0xffffffffu, va, 1);
            float lg = odd ? pv : va;
            float vl = odd ? va : pv;
            float e = __expf(lg);
            s += e;
            d += e * vl;
        }
        if (!odd) {
            int i = (mtile * 128 + t) >> 1;
            if (i < NATT) out[b * NATT + i] = d / s;
        }
    }
}

// ---------------------------------------------------------------------------
extern "C" void kernel_launch(void* const* d_in, const int* in_sizes, int n_in,
                              void* d_out, int out_size) {
    const float* img = (const float*)d_in[0];
    const float* V   = (const float*)d_in[1];
    const float* W1  = (const float*)d_in[2];
    const float* W2  = (const float*)d_in[3];
    float* out = (float*)d_out;

    cudaFuncSetAttribute(main_gemm, cudaFuncAttributeMaxDynamicSharedMemorySize,
                         SMEM_TOTAL);

    vv_kernel<<<NATT, 256>>>(V);
    gemm_small<<<dim3(5, 8, 2), 256>>>(W1, W2);
    conv_kernel<<<dim3(32, B_), 256>>>(img);
    reduce_norm_kernel<<<B_, 256>>>();
    main_gemm<<<dim3(5, B_), 256, SMEM_TOTAL>>>(out);
}

// round 16
// speedup vs baseline: 5.2763x; 1.1610x over previous
#include <cuda_runtime.h>
#include <cuda_fp16.h>
#include <math.h>
#include <stdint.h>

#define B_   128
#define CF   1024
#define R_   256
#define NATT 312
#define DV   300
#define NJP  640   // padded interleaved rows (row 2i=Q_i, 2i+1=P_i)

// ---------------- device scratch ----------------
__device__ __half g_Mh[NJP * CF];                // fp16 M, interleaved Q/P (pad rows stay 0)
__device__ __half g_T[(size_t)B_ * CF * R_];     // img fp16, natural [b][f][r]
__device__ float g_np[32 * B_ * R_];             // norm^2 partials [fc][b][r]

// ---------------- smem layout (main kernel) ----------------
#define PITCH_A 144                        // 128B + 16B pad
#define PITCH_B 528                        // 512B + 16B pad (row shift = 1 16B col)
#define SA      0                          // 128 rows * 144 = 18432
#define SB      18432                      // 64 rows * 528 = 33792
#define STAGE   52224
#define NSTG    4
#define INV_OFF (NSTG * STAGE)             // 208896
#define SMEM_TOTAL (INV_OFF + 1024)        // 209920
#define CPITCH  257                        // epilogue fp32 C pitch (floats)

#define GS_BLOCKS 80

// ---------------- PTX helpers (plain sm_80+ PTX only) ----------------
__device__ __forceinline__ uint32_t smem_u32(const void* p) {
    uint32_t a;
    asm("{ .reg .u64 t; cvta.to.shared.u64 t, %1; cvt.u32.u64 %0, t; }" : "=r"(a) : "l"(p));
    return a;
}
__device__ __forceinline__ void cp16(uint32_t dst, const void* src) {
    asm volatile("cp.async.cg.shared.global [%0], [%1], 16;" :: "r"(dst), "l"(src));
}
#define CP_COMMIT() asm volatile("cp.async.commit_group;" ::: "memory")
#define CP_WAIT(n)  asm volatile("cp.async.wait_group %0;" :: "n"(n) : "memory")

__device__ __forceinline__ void ldsm4(uint32_t& r0, uint32_t& r1, uint32_t& r2,
                                      uint32_t& r3, uint32_t addr) {
    asm volatile("ldmatrix.sync.aligned.m8n8.x4.shared.b16 {%0,%1,%2,%3}, [%4];"
                 : "=r"(r0), "=r"(r1), "=r"(r2), "=r"(r3) : "r"(addr));
}
__device__ __forceinline__ void ldsm4t(uint32_t& r0, uint32_t& r1, uint32_t& r2,
                                       uint32_t& r3, uint32_t addr) {
    asm volatile("ldmatrix.sync.aligned.m8n8.x4.trans.shared.b16 {%0,%1,%2,%3}, [%4];"
                 : "=r"(r0), "=r"(r1), "=r"(r2), "=r"(r3) : "r"(addr));
}
__device__ __forceinline__ void mma16816(float* d, const uint32_t* a,
                                         uint32_t b0, uint32_t b1) {
    asm volatile("mma.sync.aligned.m16n8k16.row.col.f32.f16.f16.f32 "
                 "{%0,%1,%2,%3}, {%4,%5,%6,%7}, {%8,%9}, {%0,%1,%2,%3};"
                 : "+f"(d[0]), "+f"(d[1]), "+f"(d[2]), "+f"(d[3])
                 : "r"(a[0]), "r"(a[1]), "r"(a[2]), "r"(a[3]), "r"(b0), "r"(b1));
}

// ---------------------------------------------------------------------------
// Fat prep kernel.
//  blocks [0, 80):    gemm_small — M interleaved fp16 (V normalized inline)
//  blocks [80, 4176): conv — img fp32 -> fp16 (same layout) + norm^2 partials
// ---------------------------------------------------------------------------
__global__ void __launch_bounds__(256)
prep_kernel(const float* __restrict__ img, const float* __restrict__ V,
            const float* __restrict__ W1, const float* __restrict__ W2) {
    const int t = threadIdx.x;

    if (blockIdx.x >= GS_BLOCKS) {
        // ================= conv part =================
        int cid = blockIdx.x - GS_BLOCKS;
        int fc = cid & 31, b = cid >> 5;
        __shared__ float4 nsm[4][64];
        int fgrp = t >> 6, rgrp = t & 63;

        float4 nrm = make_float4(0.f, 0.f, 0.f, 0.f);
        #pragma unroll
        for (int ff = 0; ff < 8; ff++) {
            int f = fc * 32 + fgrp * 8 + ff;
            size_t base = ((size_t)(b * CF + f)) * R_ + rgrp * 4;
            float4 v = *(const float4*)(img + base);
            nrm.x += v.x * v.x; nrm.y += v.y * v.y;
            nrm.z += v.z * v.z; nrm.w += v.w * v.w;
            __half h0 = __float2half(v.x), h1 = __float2half(v.y);
            __half h2 = __float2half(v.z), h3 = __float2half(v.w);
            uint2 pk;
            pk.x = (uint32_t)*(unsigned short*)&h0 | ((uint32_t)*(unsigned short*)&h1 << 16);
            pk.y = (uint32_t)*(unsigned short*)&h2 | ((uint32_t)*(unsigned short*)&h3 << 16);
            *(uint2*)(g_T + base) = pk;
        }
        nsm[fgrp][rgrp] = nrm;
        __syncthreads();
        if (t < 64) {
            float4 a = nsm[0][t], b4 = nsm[1][t], c4 = nsm[2][t], d4 = nsm[3][t];
            float4 s4 = make_float4(a.x + b4.x + c4.x + d4.x,
                                    a.y + b4.y + c4.y + d4.y,
                                    a.z + b4.z + c4.z + d4.z,
                                    a.w + b4.w + c4.w + d4.w);
            *(float4*)(g_np + ((size_t)fc * B_ + b) * R_ + t * 4) = s4;
        }
        return;
    }

    // ================= gemm_small part =================
    // idx decode: z = idx&1, bn = ((idx>>1)&7)*128, bm = (idx>>4)*64
    const int idx = blockIdx.x;
    const int z  = idx & 1;
    const int bn = ((idx >> 1) & 7) * 128;
    const int bm = (idx >> 4) * 64;
    const float* Bp = z ? W2 : W1;

    __shared__ float As[64][17];
    __shared__ float Bs[16][128];
    __shared__ float invn_sm[64];

    const int wid = t >> 5, l = t & 31;
    // per-warp: 8 V-row norms
    #pragma unroll
    for (int rr = 0; rr < 8; rr++) {
        int lrow = wid * 8 + rr;
        int gr = bm + lrow;
        float s = 0.f;
        if (gr < NATT)
            for (int k = l; k < DV; k += 32) { float x = V[(size_t)gr * DV + k]; s += x * x; }
        #pragma unroll
        for (int o = 16; o; o >>= 1) s += __shfl_xor_sync(0xffffffffu, s, o);
        if (l == 0) invn_sm[lrow] = 1.f / fmaxf(sqrtf(s), 1e-12f);
    }
    __syncthreads();

    const int tx = t & 15, ty = t >> 4;
    float acc[4][8];
    #pragma unroll
    for (int i = 0; i < 4; i++)
        #pragma unroll
        for (int j = 0; j < 8; j++) acc[i][j] = 0.f;

    for (int k0 = 0; k0 < DV; k0 += 16) {
        {   // A tile: 64x16 = 256 float4, one per thread (DV % 4 == 0)
            int row = t >> 2, kk4 = (t & 3) * 4;
            float4 v = make_float4(0.f, 0.f, 0.f, 0.f);
            int gr = bm + row, gk = k0 + kk4;
            if (gr < NATT && gk < DV) v = *(const float4*)(V + (size_t)gr * DV + gk);
            float in = invn_sm[row];
            As[row][kk4 + 0] = v.x * in; As[row][kk4 + 1] = v.y * in;
            As[row][kk4 + 2] = v.z * in; As[row][kk4 + 3] = v.w * in;
        }
        #pragma unroll
        for (int it = 0; it < 2; it++) {
            int s = it * 256 + t;
            int kk = s >> 5, n4 = (s & 31) * 4;
            float4 v = make_float4(0.f, 0.f, 0.f, 0.f);
            int gk = k0 + kk;
            if (gk < DV) v = *(const float4*)(Bp + (size_t)gk * CF + bn + n4);
            *(float4*)&Bs[kk][n4] = v;
        }
        __syncthreads();
        #pragma unroll
        for (int k = 0; k < 16; k++) {
            float a[4], bb[8];
            #pragma unroll
            for (int i = 0; i < 4; i++) a[i] = As[ty * 4 + i][k];
            float4 b0 = *(float4*)&Bs[k][tx * 4];
            float4 b1 = *(float4*)&Bs[k][64 + tx * 4];
            bb[0] = b0.x; bb[1] = b0.y; bb[2] = b0.z; bb[3] = b0.w;
            bb[4] = b1.x; bb[5] = b1.y; bb[6] = b1.z; bb[7] = b1.w;
            #pragma unroll
            for (int i = 0; i < 4; i++)
                #pragma unroll
                for (int j = 0; j < 8; j++)
                    acc[i][j] = fmaf(a[i], bb[j], acc[i][j]);
        }
        __syncthreads();
    }
    #pragma unroll
    for (int i = 0; i < 4; i++) {
        int gr = bm + ty * 4 + i;
        if (gr < NATT) {
            int row = 2 * gr + z;   // interleaved
            #pragma unroll
            for (int jj = 0; jj < 2; jj++) {
                int gc = bn + jj * 64 + tx * 4;
                unsigned short h[4];
                #pragma unroll
                for (int u = 0; u < 4; u++) {
                    __half hv = __float2half(acc[i][jj * 4 + u]);
                    h[u] = *(unsigned short*)&hv;
                }
                uint2 pk;
                pk.x = (uint32_t)h[0] | ((uint32_t)h[1] << 16);
                pk.y = (uint32_t)h[2] | ((uint32_t)h[3] << 16);
                *(uint2*)(g_Mh + (size_t)row * CF + gc) = pk;
            }
        }
    }
}

// ---------------------------------------------------------------------------
// Main: per (mtile,b): D[128,256] = A @ B where B = img_b fp16 [f][r]
// (ldmatrix.trans), single-product fp16 mma, 4-stage cp.async pipeline,
// norm-reduce prologue, fused softmax-dot epilogue.
// ---------------------------------------------------------------------------
__global__ void __launch_bounds__(256, 1)
main_gemm(float* __restrict__ out) {
    extern __shared__ char smem[];
    const uint32_t sb = smem_u32(smem);
    const int t = threadIdx.x;
    const int mtile = blockIdx.x;   // 0..4
    const int b = blockIdx.y;       // 0..127

    auto load_chunk = [&](int c, uint32_t st) {
        const int f0 = c * 64;
        // A tile: 128 rows x 128B, PITCH_A
        #pragma unroll
        for (int i = 0; i < 4; i++) {
            int s = i * 256 + t;
            int row = s >> 3, q = s & 7;
            size_t gi = (size_t)(mtile * 128 + row) * CF + f0 + q * 8;
            cp16(st + SA + row * PITCH_A + q * 16, g_Mh + gi);
        }
        // B tile: 64 f-rows x 512B (256 r fp16), PITCH_B
        #pragma unroll
        for (int i = 0; i < 8; i++) {
            int s = i * 256 + t;
            int row = s >> 5, q = s & 31;
            size_t gi = ((size_t)(b * CF + f0 + row)) * R_ + q * 8;
            cp16(st + SB + row * PITCH_B + q * 16, g_T + gi);
        }
    };

    load_chunk(0, sb);
    CP_COMMIT();
    load_chunk(1, sb + STAGE);
    CP_COMMIT();
    load_chunk(2, sb + 2 * STAGE);
    CP_COMMIT();

    // norm reduce (overlapped with cp.async latency)
    float* inv_sm = (float*)(smem + INV_OFF);
    {
        float s = 0.f;
        #pragma unroll
        for (int fc = 0; fc < 32; fc++) s += g_np[(fc * B_ + b) * R_ + t];
        inv_sm[t] = 1.f / fmaxf(sqrtf(s), 1e-12f);
    }

    const int l = t & 31, wid = t >> 5;
    const int wid_m = wid >> 1;   // 0..3 -> 32 rows each
    const int wid_n = wid & 1;    // 0..1 -> 128 cols each

    uint32_t a_rel[2];
    #pragma unroll
    for (int mt = 0; mt < 2; mt++)
        a_rel[mt] = (uint32_t)((wid_m * 32 + mt * 16 + (l & 15)) * PITCH_A + ((l >> 4) << 4));
    // B trans-ldsm base: lane -> k row (l&15), n offset ((l>>4)*8)
    const uint32_t b_rel0 = (uint32_t)((l & 15) * PITCH_B + (wid_n * 128 + (l >> 4) * 8) * 2);

    float acc[2][16][4];
    #pragma unroll
    for (int mt = 0; mt < 2; mt++)
        #pragma unroll
        for (int nf = 0; nf < 16; nf++)
            #pragma unroll
            for (int x = 0; x < 4; x++) acc[mt][nf][x] = 0.f;

    for (int c = 0; c < 16; c++) {
        if (c < 14) CP_WAIT(2);
        else if (c == 14) CP_WAIT(1);
        else CP_WAIT(0);
        __syncthreads();
        const uint32_t st = sb + (uint32_t)(c % NSTG) * STAGE;

        #pragma unroll
        for (int j = 0; j < 4; j++) {          // 4 k16 steps per chunk
            uint32_t ah[2][4];
            #pragma unroll
            for (int mt = 0; mt < 2; mt++)
                ldsm4(ah[mt][0], ah[mt][1], ah[mt][2], ah[mt][3],
                      st + SA + a_rel[mt] + j * 32);
            const uint32_t bbase = st + SB + b_rel0 + (uint32_t)j * (16 * PITCH_B);
            #pragma unroll
            for (int u = 0; u < 8; u++) {       // 8 n16 blocks of r
                uint32_t r0, r1, r2, r3;
                ldsm4t(r0, r1, r2, r3, bbase + u * 32);
                #pragma unroll
                for (int mt = 0; mt < 2; mt++) {
                    mma16816(acc[mt][2 * u + 0], ah[mt], r0, r1);
                    mma16816(acc[mt][2 * u + 1], ah[mt], r2, r3);
                }
            }
        }
        if (c + 3 < 16) {
            load_chunk(c + 3, sb + (uint32_t)((c + 3) % NSTG) * STAGE);
            CP_COMMIT();
        }
    }
    __syncthreads();

    // ---- epilogue: stage C in smem, per-row softmax-dot on Q/P pairs ----
    float* Cs = (float*)smem;
    const int g = l >> 2, tig = l & 3;
    #pragma unroll
    for (int mt = 0; mt < 2; mt++)
        #pragma unroll
        for (int nf = 0; nf < 16; nf++) {
            int row = wid_m * 32 + mt * 16 + g;
            int col = wid_n * 128 + nf * 8 + tig * 2;
            Cs[row * CPITCH + col]           = acc[mt][nf][0];
            Cs[row * CPITCH + col + 1]       = acc[mt][nf][1];
            Cs[(row + 8) * CPITCH + col]     = acc[mt][nf][2];
            Cs[(row + 8) * CPITCH + col + 1] = acc[mt][nf][3];
        }
    __syncthreads();

    if (t < 128) {
        float s = 0.f, d = 0.f;
        const int odd = t & 1;
        #pragma unroll 8
        for (int j = 0; j < 256; j++) {
            float va = Cs[t * CPITCH + j] * inv_sm[j];
            float pv = __shfl_xor_sync(0xffffffffu, va, 1);
            float lg = odd ? pv : va;
            float vl = odd ? va : pv;
            float e = __expf(lg);
            s += e;
            d += e * vl;
        }
        if (!odd) {
            int i = (mtile * 128 + t) >> 1;
            if (i < NATT) out[b * NATT + i] = d / s;
        }
    }
}

// ---------------------------------------------------------------------------
extern "C" void kernel_launch(void* const* d_in, const int* in_sizes, int n_in,
                              void* d_out, int out_size) {
    const float* img = (const float*)d_in[0];
    const float* V   = (const float*)d_in[1];
    const float* W1  = (const float*)d_in[2];
    const float* W2  = (const float*)d_in[3];
    float* out = (float*)d_out;

    cudaFuncSetAttribute(main_gemm, cudaFuncAttributeMaxDynamicSharedMemorySize,
                         SMEM_TOTAL);

    prep_kernel<<<GS_BLOCKS + 32 * B_, 256>>>(img, V, W1, W2);
    main_gemm<<<dim3(5, B_), 256, SMEM_TOTAL>>>(out);
}

// round 17
// speedup vs baseline: 5.3911x; 1.0218x over previous
#include <cuda_runtime.h>
#include <cuda_fp16.h>
#include <math.h>
#include <stdint.h>

#define B_   128
#define CF   1024
#define R_   256
#define NATT 312
#define DV   300
#define NJP  640   // padded interleaved rows (row 2i=Q_i, 2i+1=P_i)

// ---------------- device scratch ----------------
__device__ __half g_Mh[NJP * CF];                // fp16 M, interleaved Q/P (pad rows stay 0)
__device__ __half g_T[(size_t)B_ * CF * R_];     // img fp16, natural [b][f][r]
__device__ float g_np[32 * B_ * R_];             // norm^2 partials [fc][b][r]

// ---------------- smem layout (main kernel) ----------------
#define PITCH_A 144                        // 128B + 16B pad
#define PITCH_B 528                        // 512B + 16B pad
#define SA      0                          // 128 rows * 144 = 18432
#define SB      18432                      // 64 rows * 528 = 33792
#define STAGE   52224
#define NSTG    4
#define INV_OFF (NSTG * STAGE)             // 208896
#define SMEM_TOTAL (INV_OFF + 1024)        // 209920
#define CPITCH  257                        // epilogue fp32 C pitch (floats)

#define GS_BLOCKS 80

// ---------------- PTX helpers (plain sm_80+ PTX only) ----------------
__device__ __forceinline__ uint32_t smem_u32(const void* p) {
    uint32_t a;
    asm("{ .reg .u64 t; cvta.to.shared.u64 t, %1; cvt.u32.u64 %0, t; }" : "=r"(a) : "l"(p));
    return a;
}
__device__ __forceinline__ void cp16(uint32_t dst, const void* src) {
    asm volatile("cp.async.cg.shared.global [%0], [%1], 16;" :: "r"(dst), "l"(src));
}
#define CP_COMMIT() asm volatile("cp.async.commit_group;" ::: "memory")
#define CP_WAIT(n)  asm volatile("cp.async.wait_group %0;" :: "n"(n) : "memory")

__device__ __forceinline__ void ldsm4(uint32_t& r0, uint32_t& r1, uint32_t& r2,
                                      uint32_t& r3, uint32_t addr) {
    asm volatile("ldmatrix.sync.aligned.m8n8.x4.shared.b16 {%0,%1,%2,%3}, [%4];"
                 : "=r"(r0), "=r"(r1), "=r"(r2), "=r"(r3) : "r"(addr));
}
__device__ __forceinline__ void ldsm4t(uint32_t& r0, uint32_t& r1, uint32_t& r2,
                                       uint32_t& r3, uint32_t addr) {
    asm volatile("ldmatrix.sync.aligned.m8n8.x4.trans.shared.b16 {%0,%1,%2,%3}, [%4];"
                 : "=r"(r0), "=r"(r1), "=r"(r2), "=r"(r3) : "r"(addr));
}
__device__ __forceinline__ void mma16816(float* d, const uint32_t* a,
                                         uint32_t b0, uint32_t b1) {
    asm volatile("mma.sync.aligned.m16n8k16.row.col.f32.f16.f16.f32 "
                 "{%0,%1,%2,%3}, {%4,%5,%6,%7}, {%8,%9}, {%0,%1,%2,%3};"
                 : "+f"(d[0]), "+f"(d[1]), "+f"(d[2]), "+f"(d[3])
                 : "r"(a[0]), "r"(a[1]), "r"(a[2]), "r"(a[3]), "r"(b0), "r"(b1));
}

// ---------------------------------------------------------------------------
// Fat prep kernel.
//  blocks [0, 80):    gemm_small — M interleaved fp16 (V normalized inline)
//  blocks [80, 4176): conv — img fp32 -> fp16 (same layout) + norm^2 partials
// ---------------------------------------------------------------------------
__global__ void __launch_bounds__(256)
prep_kernel(const float* __restrict__ img, const float* __restrict__ V,
            const float* __restrict__ W1, const float* __restrict__ W2) {
    const int t = threadIdx.x;

    if (blockIdx.x >= GS_BLOCKS) {
        // ================= conv part =================
        int cid = blockIdx.x - GS_BLOCKS;
        int fc = cid & 31, b = cid >> 5;
        __shared__ float4 nsm[4][64];
        int fgrp = t >> 6, rgrp = t & 63;

        float4 nrm = make_float4(0.f, 0.f, 0.f, 0.f);
        #pragma unroll
        for (int ff = 0; ff < 8; ff++) {
            int f = fc * 32 + fgrp * 8 + ff;
            size_t base = ((size_t)(b * CF + f)) * R_ + rgrp * 4;
            float4 v = *(const float4*)(img + base);
            nrm.x += v.x * v.x; nrm.y += v.y * v.y;
            nrm.z += v.z * v.z; nrm.w += v.w * v.w;
            __half h0 = __float2half(v.x), h1 = __float2half(v.y);
            __half h2 = __float2half(v.z), h3 = __float2half(v.w);
            uint2 pk;
            pk.x = (uint32_t)*(unsigned short*)&h0 | ((uint32_t)*(unsigned short*)&h1 << 16);
            pk.y = (uint32_t)*(unsigned short*)&h2 | ((uint32_t)*(unsigned short*)&h3 << 16);
            *(uint2*)(g_T + base) = pk;
        }
        nsm[fgrp][rgrp] = nrm;
        __syncthreads();
        if (t < 64) {
            float4 a = nsm[0][t], b4 = nsm[1][t], c4 = nsm[2][t], d4 = nsm[3][t];
            float4 s4 = make_float4(a.x + b4.x + c4.x + d4.x,
                                    a.y + b4.y + c4.y + d4.y,
                                    a.z + b4.z + c4.z + d4.z,
                                    a.w + b4.w + c4.w + d4.w);
            *(float4*)(g_np + ((size_t)fc * B_ + b) * R_ + t * 4) = s4;
        }
        return;
    }

    // ================= gemm_small part =================
    const int idx = blockIdx.x;
    const int z  = idx & 1;
    const int bn = ((idx >> 1) & 7) * 128;
    const int bm = (idx >> 4) * 64;
    const float* Bp = z ? W2 : W1;

    __shared__ float As[64][17];
    __shared__ float Bs[16][128];
    __shared__ float invn_sm[64];

    const int wid = t >> 5, l = t & 31;
    #pragma unroll
    for (int rr = 0; rr < 8; rr++) {
        int lrow = wid * 8 + rr;
        int gr = bm + lrow;
        float s = 0.f;
        if (gr < NATT)
            for (int k = l; k < DV; k += 32) { float x = V[(size_t)gr * DV + k]; s += x * x; }
        #pragma unroll
        for (int o = 16; o; o >>= 1) s += __shfl_xor_sync(0xffffffffu, s, o);
        if (l == 0) invn_sm[lrow] = 1.f / fmaxf(sqrtf(s), 1e-12f);
    }
    __syncthreads();

    const int tx = t & 15, ty = t >> 4;
    float acc[4][8];
    #pragma unroll
    for (int i = 0; i < 4; i++)
        #pragma unroll
        for (int j = 0; j < 8; j++) acc[i][j] = 0.f;

    for (int k0 = 0; k0 < DV; k0 += 16) {
        {
            int row = t >> 2, kk4 = (t & 3) * 4;
            float4 v = make_float4(0.f, 0.f, 0.f, 0.f);
            int gr = bm + row, gk = k0 + kk4;
            if (gr < NATT && gk < DV) v = *(const float4*)(V + (size_t)gr * DV + gk);
            float in = invn_sm[row];
            As[row][kk4 + 0] = v.x * in; As[row][kk4 + 1] = v.y * in;
            As[row][kk4 + 2] = v.z * in; As[row][kk4 + 3] = v.w * in;
        }
        #pragma unroll
        for (int it = 0; it < 2; it++) {
            int s = it * 256 + t;
            int kk = s >> 5, n4 = (s & 31) * 4;
            float4 v = make_float4(0.f, 0.f, 0.f, 0.f);
            int gk = k0 + kk;
            if (gk < DV) v = *(const float4*)(Bp + (size_t)gk * CF + bn + n4);
            *(float4*)&Bs[kk][n4] = v;
        }
        __syncthreads();
        #pragma unroll
        for (int k = 0; k < 16; k++) {
            float a[4], bb[8];
            #pragma unroll
            for (int i = 0; i < 4; i++) a[i] = As[ty * 4 + i][k];
            float4 b0 = *(float4*)&Bs[k][tx * 4];
            float4 b1 = *(float4*)&Bs[k][64 + tx * 4];
            bb[0] = b0.x; bb[1] = b0.y; bb[2] = b0.z; bb[3] = b0.w;
            bb[4] = b1.x; bb[5] = b1.y; bb[6] = b1.z; bb[7] = b1.w;
            #pragma unroll
            for (int i = 0; i < 4; i++)
                #pragma unroll
                for (int j = 0; j < 8; j++)
                    acc[i][j] = fmaf(a[i], bb[j], acc[i][j]);
        }
        __syncthreads();
    }
    #pragma unroll
    for (int i = 0; i < 4; i++) {
        int gr = bm + ty * 4 + i;
        if (gr < NATT) {
            int row = 2 * gr + z;   // interleaved
            #pragma unroll
            for (int jj = 0; jj < 2; jj++) {
                int gc = bn + jj * 64 + tx * 4;
                unsigned short h[4];
                #pragma unroll
                for (int u = 0; u < 4; u++) {
                    __half hv = __float2half(acc[i][jj * 4 + u]);
                    h[u] = *(unsigned short*)&hv;
                }
                uint2 pk;
                pk.x = (uint32_t)h[0] | ((uint32_t)h[1] << 16);
                pk.y = (uint32_t)h[2] | ((uint32_t)h[3] << 16);
                *(uint2*)(g_Mh + (size_t)row * CF + gc) = pk;
            }
        }
    }
}

// ---------------------------------------------------------------------------
// Main: 512 threads, warp grid 4m x 4n (warp tile 32x64).
// Per (mtile,b): D[128,256] = A @ B, B via ldmatrix.trans, 4-stage cp.async,
// norm-reduce prologue, fused softmax-dot epilogue.
// ---------------------------------------------------------------------------
__global__ void __launch_bounds__(512, 1)
main_gemm(float* __restrict__ out) {
    extern __shared__ char smem[];
    const uint32_t sb = smem_u32(smem);
    const int t = threadIdx.x;
    const int mtile = blockIdx.x;   // 0..4
    const int b = blockIdx.y;       // 0..127

    auto load_chunk = [&](int c, uint32_t st) {
        const int f0 = c * 64;
        // A tile: 128 rows x 8 x 16B = 1024 slots / 512 threads = 2
        #pragma unroll
        for (int i = 0; i < 2; i++) {
            int s = i * 512 + t;
            int row = s >> 3, q = s & 7;
            size_t gi = (size_t)(mtile * 128 + row) * CF + f0 + q * 8;
            cp16(st + SA + row * PITCH_A + q * 16, g_Mh + gi);
        }
        // B tile: 64 rows x 32 x 16B = 2048 slots / 512 threads = 4
        #pragma unroll
        for (int i = 0; i < 4; i++) {
            int s = i * 512 + t;
            int row = s >> 5, q = s & 31;
            size_t gi = ((size_t)(b * CF + f0 + row)) * R_ + q * 8;
            cp16(st + SB + row * PITCH_B + q * 16, g_T + gi);
        }
    };

    load_chunk(0, sb);
    CP_COMMIT();
    load_chunk(1, sb + STAGE);
    CP_COMMIT();
    load_chunk(2, sb + 2 * STAGE);
    CP_COMMIT();

    // norm reduce (overlapped with cp.async latency)
    float* inv_sm = (float*)(smem + INV_OFF);
    if (t < 256) {
        float s = 0.f;
        #pragma unroll
        for (int fc = 0; fc < 32; fc++) s += g_np[(fc * B_ + b) * R_ + t];
        inv_sm[t] = 1.f / fmaxf(sqrtf(s), 1e-12f);
    }

    const int l = t & 31, wid = t >> 5;
    const int wid_m = wid >> 2;   // 0..3 -> 32 rows each
    const int wid_n = wid & 3;    // 0..3 -> 64 cols each

    uint32_t a_rel[2];
    #pragma unroll
    for (int mt = 0; mt < 2; mt++)
        a_rel[mt] = (uint32_t)((wid_m * 32 + mt * 16 + (l & 15)) * PITCH_A + ((l >> 4) << 4));
    const uint32_t b_rel0 = (uint32_t)((l & 15) * PITCH_B + (wid_n * 64 + (l >> 4) * 8) * 2);

    float acc[2][8][4];
    #pragma unroll
    for (int mt = 0; mt < 2; mt++)
        #pragma unroll
        for (int nf = 0; nf < 8; nf++)
            #pragma unroll
            for (int x = 0; x < 4; x++) acc[mt][nf][x] = 0.f;

    for (int c = 0; c < 16; c++) {
        if (c < 14) CP_WAIT(2);
        else if (c == 14) CP_WAIT(1);
        else CP_WAIT(0);
        __syncthreads();
        const uint32_t st = sb + (uint32_t)(c % NSTG) * STAGE;

        #pragma unroll
        for (int j = 0; j < 4; j++) {          // 4 k16 steps per chunk
            uint32_t ah[2][4];
            #pragma unroll
            for (int mt = 0; mt < 2; mt++)
                ldsm4(ah[mt][0], ah[mt][1], ah[mt][2], ah[mt][3],
                      st + SA + a_rel[mt] + j * 32);
            const uint32_t bbase = st + SB + b_rel0 + (uint32_t)j * (16 * PITCH_B);
            #pragma unroll
            for (int u = 0; u < 4; u++) {       // 4 n16 blocks of r
                uint32_t r0, r1, r2, r3;
                ldsm4t(r0, r1, r2, r3, bbase + u * 32);
                #pragma unroll
                for (int mt = 0; mt < 2; mt++) {
                    mma16816(acc[mt][2 * u + 0], ah[mt], r0, r1);
                    mma16816(acc[mt][2 * u + 1], ah[mt], r2, r3);
                }
            }
        }
        if (c + 3 < 16) {
            load_chunk(c + 3, sb + (uint32_t)((c + 3) % NSTG) * STAGE);
            CP_COMMIT();
        }
    }
    __syncthreads();

    // ---- epilogue: stage C in smem, per-row softmax-dot on Q/P pairs ----
    float* Cs = (float*)smem;
    const int g = l >> 2, tig = l & 3;
    #pragma unroll
    for (int mt = 0; mt < 2; mt++)
        #pragma unroll
        for (int nf = 0; nf < 8; nf++) {
            int row = wid_m * 32 + mt * 16 + g;
            int col = wid_n * 64 + nf * 8 + tig * 2;
            Cs[row * CPITCH + col]           = acc[mt][nf][0];
            Cs[row * CPITCH + col + 1]       = acc[mt][nf][1];
            Cs[(row + 8) * CPITCH + col]     = acc[mt][nf][2];
            Cs[(row + 8) * CPITCH + col + 1] = acc[mt][nf][3];
        }
    __syncthreads();

    if (t < 128) {
        float s = 0.f, d = 0.f;
        const int odd = t & 1;
        #pragma unroll 8
        for (int j = 0; j < 256; j++) {
            float va = Cs[t * CPITCH + j] * inv_sm[j];
            float pv = __shfl_xor_sync(0xffffffffu, va, 1);
            float lg = odd ? pv : va;
            float vl = odd ? va : pv;
            float e = __expf(lg);
            s += e;
            d += e * vl;
        }
        if (!odd) {
            int i = (mtile * 128 + t) >> 1;
            if (i < NATT) out[b * NATT + i] = d / s;
        }
    }
}

// ---------------------------------------------------------------------------
extern "C" void kernel_launch(void* const* d_in, const int* in_sizes, int n_in,
                              void* d_out, int out_size) {
    const float* img = (const float*)d_in[0];
    const float* V   = (const float*)d_in[1];
    const float* W1  = (const float*)d_in[2];
    const float* W2  = (const float*)d_in[3];
    float* out = (float*)d_out;

    cudaFuncSetAttribute(main_gemm, cudaFuncAttributeMaxDynamicSharedMemorySize,
                         SMEM_TOTAL);

    prep_kernel<<<GS_BLOCKS + 32 * B_, 256>>>(img, V, W1, W2);
    main_gemm<<<dim3(5, B_), 512, SMEM_TOTAL>>>(out);
}